// round 1
// baseline (speedup 1.0000x reference)
#include <cuda_runtime.h>
#include <cstdint>
#include <math.h>

// ---------------- problem constants ----------------
#define ALPHAC 1.702f
#define LIMITC 7.0f
#define NTOK   1024
#define HD     2880          // hidden dim
#define NE     16            // experts
#define ID     2880          // intermediate dim
#define TOPK   4
#define NSLOT  (NTOK*TOPK)   // 4096
#define SLOTPAD (NSLOT+64)   // padding so tile overreads stay in-bounds

// ---------------- device scratch (static: no runtime allocs allowed) -------
__device__ int   g_topk_eid[NSLOT];
__device__ float g_topk_prob[NSLOT];
__device__ int   g_expert_off[NE+1];
__device__ int   g_slot_token[SLOTPAD];
__device__ int   g_token_slot[NSLOT];
__device__ float g_act [(size_t)SLOTPAD*ID];   // ~48 MB
__device__ float g_out2[(size_t)SLOTPAD*HD];   // ~48 MB

// ---------------- 1. router: logits + top4 + softmax -----------------------
__global__ __launch_bounds__(256) void router_kernel(
    const float* __restrict__ hidden,
    const float* __restrict__ rw,
    const float* __restrict__ rb)
{
    const int t = blockIdx.x;
    const float* __restrict__ x = hidden + (size_t)t * HD;
    const int warp = threadIdx.x >> 5, lane = threadIdx.x & 31;
    __shared__ float logits[NE];

    const int e0 = warp * 2, e1 = e0 + 1;
    const float* __restrict__ w0 = rw + (size_t)e0 * HD;
    const float* __restrict__ w1r = rw + (size_t)e1 * HD;
    float s0 = 0.f, s1 = 0.f;
    for (int k = lane; k < HD; k += 32) {
        float xv = x[k];
        s0 = fmaf(xv, w0[k], s0);
        s1 = fmaf(xv, w1r[k], s1);
    }
    #pragma unroll
    for (int o = 16; o; o >>= 1) {
        s0 += __shfl_xor_sync(0xffffffffu, s0, o);
        s1 += __shfl_xor_sync(0xffffffffu, s1, o);
    }
    if (lane == 0) { logits[e0] = s0 + rb[e0]; logits[e1] = s1 + rb[e1]; }
    __syncthreads();

    if (threadIdx.x == 0) {
        float v[NE];
        #pragma unroll
        for (int e = 0; e < NE; e++) v[e] = logits[e];
        int   ids [TOPK];
        float vals[TOPK];
        #pragma unroll
        for (int kk = 0; kk < TOPK; kk++) {
            int bi = 0; float bv = -INFINITY;
            #pragma unroll
            for (int e = 0; e < NE; e++)
                if (v[e] > bv) { bv = v[e]; bi = e; }
            ids[kk] = bi; vals[kk] = bv; v[bi] = -INFINITY;
        }
        float m = vals[0], ssum = 0.f, p[TOPK];
        #pragma unroll
        for (int kk = 0; kk < TOPK; kk++) { p[kk] = __expf(vals[kk] - m); ssum += p[kk]; }
        float inv = 1.f / ssum;
        #pragma unroll
        for (int kk = 0; kk < TOPK; kk++) {
            g_topk_eid [t*TOPK + kk] = ids[kk];
            g_topk_prob[t*TOPK + kk] = p[kk] * inv;
        }
    }
}

// ---------------- 2. build per-expert token lists (deterministic) ----------
// One block, 16 warps; warp e compacts tokens choosing expert e, in token order.
__global__ __launch_bounds__(512) void build_kernel()
{
    __shared__ int counts[NE];
    __shared__ int offs[NE+1];
    const int warp = threadIdx.x >> 5, lane = threadIdx.x & 31;
    const int e = warp;

    // pass 1: count
    int cnt = 0;
    for (int base = 0; base < NTOK; base += 32) {
        const int t = base + lane;
        bool match = false;
        #pragma unroll
        for (int kk = 0; kk < TOPK; kk++) match |= (g_topk_eid[t*TOPK + kk] == e);
        cnt += __popc(__ballot_sync(0xffffffffu, match));
    }
    if (lane == 0) counts[e] = cnt;
    __syncthreads();
    if (threadIdx.x == 0) {
        int acc = 0;
        for (int i = 0; i < NE; i++) { offs[i] = acc; acc += counts[i]; }
        offs[NE] = acc;
        for (int i = 0; i <= NE; i++) g_expert_off[i] = offs[i];
    }
    __syncthreads();

    // pass 2: compact in token order via ballot rank
    int run = offs[e];
    for (int base = 0; base < NTOK; base += 32) {
        const int t = base + lane;
        int kkm = -1;
        #pragma unroll
        for (int kk = 0; kk < TOPK; kk++)
            if (g_topk_eid[t*TOPK + kk] == e) kkm = kk;
        unsigned mask = __ballot_sync(0xffffffffu, kkm >= 0);
        int rank = __popc(mask & ((1u << lane) - 1u));
        if (kkm >= 0) {
            int slot = run + rank;
            g_slot_token[slot] = t;
            g_token_slot[t*TOPK + kkm] = slot;
        }
        run += __popc(mask);
    }
}

// ---------------- 3. GEMM1: gu = X_gather @ w1[e]^T + b1, fused activation -
// Tile: BM=64 (slots), BN=128 (gu cols = 64 i's), BK=16. 256 thr, 4x8/thread.
__global__ __launch_bounds__(256) void gemm1_kernel(
    const float* __restrict__ hidden,
    const float* __restrict__ w1,
    const float* __restrict__ b1)
{
    const int e   = blockIdx.z;
    const int off = g_expert_off[e];
    const int cnt = g_expert_off[e+1] - off;
    const int m0  = blockIdx.y * 64;
    if (m0 >= cnt) return;
    const int n0  = blockIdx.x * 128;
    const int tid = threadIdx.x;
    const int trow = tid >> 4;     // 0..15 (rows of 4)
    const int tcol = tid & 15;     // 0..15 (cols of 8)

    __shared__ float As[16][64];
    __shared__ float Bs[16][128];

    // A loader: 1 float4/thread (64 rows x 4 f4)
    const int a_row = tid >> 2;
    const int a_k   = (tid & 3) << 2;
    const int a_m   = m0 + a_row;
    const int a_tok = (a_m < cnt) ? g_slot_token[off + a_m] : 0;
    const float* __restrict__ aptr = hidden + (size_t)a_tok * HD + a_k;

    // B loader: 2 float4/thread (128 rows x 4 f4). row=tid>>1, k base=(tid&1)*8
    const int b_row = tid >> 1;
    const int b_k   = (tid & 1) << 3;
    const float* __restrict__ bptr =
        w1 + (size_t)e * (2*(size_t)ID) * HD + (size_t)(n0 + b_row) * HD + b_k;

    float acc[4][8];
    #pragma unroll
    for (int i = 0; i < 4; i++)
        #pragma unroll
        for (int j = 0; j < 8; j++) acc[i][j] = 0.f;

    for (int k0 = 0; k0 < HD; k0 += 16) {
        float4 av  = *(const float4*)(aptr + k0);
        float4 bv0 = *(const float4*)(bptr + k0);
        float4 bv1 = *(const float4*)(bptr + k0 + 4);
        __syncthreads();
        As[a_k+0][a_row] = av.x;  As[a_k+1][a_row] = av.y;
        As[a_k+2][a_row] = av.z;  As[a_k+3][a_row] = av.w;
        Bs[b_k+0][b_row] = bv0.x; Bs[b_k+1][b_row] = bv0.y;
        Bs[b_k+2][b_row] = bv0.z; Bs[b_k+3][b_row] = bv0.w;
        Bs[b_k+4][b_row] = bv1.x; Bs[b_k+5][b_row] = bv1.y;
        Bs[b_k+6][b_row] = bv1.z; Bs[b_k+7][b_row] = bv1.w;
        __syncthreads();
        #pragma unroll
        for (int kk = 0; kk < 16; kk++) {
            float a[4], b[8];
            *(float4*)a     = *(const float4*)&As[kk][trow << 2];
            *(float4*)b     = *(const float4*)&Bs[kk][tcol << 3];
            *(float4*)(b+4) = *(const float4*)&Bs[kk][(tcol << 3) + 4];
            #pragma unroll
            for (int i = 0; i < 4; i++)
                #pragma unroll
                for (int j = 0; j < 8; j++)
                    acc[i][j] = fmaf(a[i], b[j], acc[i][j]);
        }
    }

    // epilogue: pair (gate,up) -> activation, write act[slot][i]
    const float* __restrict__ b1e = b1 + (size_t)e * (2*ID);
    #pragma unroll
    for (int im = 0; im < 4; im++) {
        const int m = m0 + (trow << 2) + im;
        if (m >= cnt) continue;
        float* __restrict__ arow = g_act + (size_t)(off + m) * ID;
        #pragma unroll
        for (int j = 0; j < 4; j++) {
            const int ng = n0 + (tcol << 3) + 2*j;   // even: gate row; +1: up row
            float g = acc[im][2*j]   + b1e[ng];
            float u = acc[im][2*j+1] + b1e[ng + 1];
            g = fminf(g, LIMITC);
            u = fminf(fmaxf(u, -LIMITC), LIMITC);
            float sig = 1.f / (1.f + __expf(-ALPHAC * g));
            arow[ng >> 1] = (u + 1.f) * (g * sig);
        }
    }
}

// ---------------- 4. GEMM2: out_e = act @ w2[e]^T + b2 ---------------------
// Tile: BM=64, BN=64, BK=16. 256 thr, 4x4/thread.
__global__ __launch_bounds__(256) void gemm2_kernel(
    const float* __restrict__ w2,
    const float* __restrict__ b2)
{
    const int e   = blockIdx.z;
    const int off = g_expert_off[e];
    const int cnt = g_expert_off[e+1] - off;
    const int m0  = blockIdx.y * 64;
    if (m0 >= cnt) return;
    const int n0  = blockIdx.x * 64;
    const int tid = threadIdx.x;
    const int trow = tid >> 4, tcol = tid & 15;

    __shared__ float As[16][64];
    __shared__ float Bs[16][64];

    const int l_row = tid >> 2;
    const int l_k   = (tid & 3) << 2;
    const float* __restrict__ aptr = g_act + (size_t)(off + m0 + l_row) * ID + l_k;
    const float* __restrict__ bptr =
        w2 + (size_t)e * HD * (size_t)ID + (size_t)(n0 + l_row) * ID + l_k;

    float acc[4][4];
    #pragma unroll
    for (int i = 0; i < 4; i++)
        #pragma unroll
        for (int j = 0; j < 4; j++) acc[i][j] = 0.f;

    for (int k0 = 0; k0 < ID; k0 += 16) {
        float4 av = *(const float4*)(aptr + k0);
        float4 bv = *(const float4*)(bptr + k0);
        __syncthreads();
        As[l_k+0][l_row] = av.x; As[l_k+1][l_row] = av.y;
        As[l_k+2][l_row] = av.z; As[l_k+3][l_row] = av.w;
        Bs[l_k+0][l_row] = bv.x; Bs[l_k+1][l_row] = bv.y;
        Bs[l_k+2][l_row] = bv.z; Bs[l_k+3][l_row] = bv.w;
        __syncthreads();
        #pragma unroll
        for (int kk = 0; kk < 16; kk++) {
            float a[4], b[4];
            *(float4*)a = *(const float4*)&As[kk][trow << 2];
            *(float4*)b = *(const float4*)&Bs[kk][tcol << 2];
            #pragma unroll
            for (int i = 0; i < 4; i++)
                #pragma unroll
                for (int j = 0; j < 4; j++)
                    acc[i][j] = fmaf(a[i], b[j], acc[i][j]);
        }
    }

    const float* __restrict__ b2e = b2 + (size_t)e * HD;
    #pragma unroll
    for (int im = 0; im < 4; im++) {
        const int m = m0 + (trow << 2) + im;
        if (m >= cnt) continue;
        float* __restrict__ orow = g_out2 + (size_t)(off + m) * HD;
        #pragma unroll
        for (int j = 0; j < 4; j++) {
            const int n = n0 + (tcol << 2) + j;
            orow[n] = acc[im][j] + b2e[n];
        }
    }
}

// ---------------- 5. combine: out[t] = sum_k p_k * out2[slot(t,k)] ---------
__global__ __launch_bounds__(256) void combine_kernel(float* __restrict__ out)
{
    const int t = blockIdx.x;
    __shared__ int   ss[TOPK];
    __shared__ float pp[TOPK];
    if (threadIdx.x < TOPK) {
        ss[threadIdx.x] = g_token_slot[t*TOPK + threadIdx.x];
        pp[threadIdx.x] = g_topk_prob[t*TOPK + threadIdx.x];
    }
    __syncthreads();
    const int   s0 = ss[0], s1 = ss[1], s2 = ss[2], s3 = ss[3];
    const float p0 = pp[0], p1 = pp[1], p2 = pp[2], p3 = pp[3];
    const float* __restrict__ r0 = g_out2 + (size_t)s0 * HD;
    const float* __restrict__ r1 = g_out2 + (size_t)s1 * HD;
    const float* __restrict__ r2 = g_out2 + (size_t)s2 * HD;
    const float* __restrict__ r3 = g_out2 + (size_t)s3 * HD;
    float* __restrict__ o = out + (size_t)t * HD;
    for (int h = threadIdx.x; h < HD; h += blockDim.x) {
        o[h] = p0*r0[h] + p1*r1[h] + p2*r2[h] + p3*r3[h];
    }
}

// ---------------- launch ----------------------------------------------------
extern "C" void kernel_launch(void* const* d_in, const int* in_sizes, int n_in,
                              void* d_out, int out_size)
{
    const float* hidden   = (const float*)d_in[0];
    const float* router_w = (const float*)d_in[1];
    const float* router_b = (const float*)d_in[2];
    const float* w1       = (const float*)d_in[3];
    const float* b1       = (const float*)d_in[4];
    const float* w2       = (const float*)d_in[5];
    const float* b2       = (const float*)d_in[6];
    float* out = (float*)d_out;

    router_kernel<<<NTOK, 256>>>(hidden, router_w, router_b);
    build_kernel<<<1, 512>>>();
    // GEMM1: n tiles = 2*ID/128 = 45, m tiles = 1024/64 = 16, experts = 16
    gemm1_kernel<<<dim3(45, 16, NE), 256>>>(hidden, w1, b1);
    // GEMM2: n tiles = HD/64 = 45
    gemm2_kernel<<<dim3(45, 16, NE), 256>>>(w2, b2);
    combine_kernel<<<NTOK, 256>>>(out);
}

// round 6
// speedup vs baseline: 3.1296x; 3.1296x over previous
#include <cuda_runtime.h>
#include <cstdint>
#include <math.h>

// ---------------- problem constants ----------------
#define ALPHAC 1.702f
#define LIMITC 7.0f
#define NTOK   1024
#define HD     2880
#define NE     16
#define ID     2880
#define TOPK   4
#define NSLOT  (NTOK*TOPK)
#define SLOTPAD (NSLOT+128)

// ---------------- device scratch -------------------------------------------
__device__ int   g_topk_eid[NSLOT];
__device__ float g_topk_prob[NSLOT];
__device__ int   g_expert_off[NE+1];
__device__ int   g_slot_token[SLOTPAD];
__device__ int   g_token_slot[NSLOT];
__device__ float g_act [(size_t)SLOTPAD*ID];
__device__ float g_out2[(size_t)SLOTPAD*HD];

// ---------------- helpers ---------------------------------------------------
__device__ __forceinline__ float to_tf32(float x) {
    float r; asm("cvt.rna.tf32.f32 %0, %1;" : "=f"(r) : "f"(x)); return r;
}
__device__ __forceinline__ void mma_tf32_16n8k8(float* d, const uint32_t* a, const uint32_t* b) {
    asm volatile(
        "mma.sync.aligned.m16n8k8.row.col.f32.tf32.tf32.f32 "
        "{%0,%1,%2,%3}, {%4,%5,%6,%7}, {%8,%9}, {%0,%1,%2,%3};\n"
        : "+f"(d[0]), "+f"(d[1]), "+f"(d[2]), "+f"(d[3])
        : "r"(a[0]), "r"(a[1]), "r"(a[2]), "r"(a[3]), "r"(b[0]), "r"(b[1]));
}
__device__ __forceinline__ void cvt_store4(float* dst, float4 v) {
    v.x = to_tf32(v.x); v.y = to_tf32(v.y); v.z = to_tf32(v.z); v.w = to_tf32(v.w);
    *(float4*)dst = v;
}

// ---------------- 1. router (exact fp32) ------------------------------------
__global__ __launch_bounds__(256) void router_kernel(
    const float* __restrict__ hidden,
    const float* __restrict__ rw,
    const float* __restrict__ rb)
{
    const int t = blockIdx.x;
    const float* __restrict__ x = hidden + (size_t)t * HD;
    const int warp = threadIdx.x >> 5, lane = threadIdx.x & 31;
    __shared__ float logits[NE];

    const int e0 = warp * 2, e1 = e0 + 1;
    const float* __restrict__ w0 = rw + (size_t)e0 * HD;
    const float* __restrict__ w1r = rw + (size_t)e1 * HD;
    float s0 = 0.f, s1 = 0.f;
    for (int k = lane; k < HD; k += 32) {
        float xv = x[k];
        s0 = fmaf(xv, w0[k], s0);
        s1 = fmaf(xv, w1r[k], s1);
    }
    #pragma unroll
    for (int o = 16; o; o >>= 1) {
        s0 += __shfl_xor_sync(0xffffffffu, s0, o);
        s1 += __shfl_xor_sync(0xffffffffu, s1, o);
    }
    if (lane == 0) { logits[e0] = s0 + rb[e0]; logits[e1] = s1 + rb[e1]; }
    __syncthreads();

    if (threadIdx.x == 0) {
        float v[NE];
        #pragma unroll
        for (int e = 0; e < NE; e++) v[e] = logits[e];
        int ids[TOPK]; float vals[TOPK];
        #pragma unroll
        for (int kk = 0; kk < TOPK; kk++) {
            int bi = 0; float bv = -INFINITY;
            #pragma unroll
            for (int e = 0; e < NE; e++)
                if (v[e] > bv) { bv = v[e]; bi = e; }
            ids[kk] = bi; vals[kk] = bv; v[bi] = -INFINITY;
        }
        float m = vals[0], ssum = 0.f, p[TOPK];
        #pragma unroll
        for (int kk = 0; kk < TOPK; kk++) { p[kk] = __expf(vals[kk] - m); ssum += p[kk]; }
        float inv = 1.f / ssum;
        #pragma unroll
        for (int kk = 0; kk < TOPK; kk++) {
            g_topk_eid [t*TOPK + kk] = ids[kk];
            g_topk_prob[t*TOPK + kk] = p[kk] * inv;
        }
    }
}

// ---------------- 2. build per-expert token lists ---------------------------
__global__ __launch_bounds__(512) void build_kernel()
{
    __shared__ int counts[NE];
    __shared__ int offs[NE+1];
    const int warp = threadIdx.x >> 5, lane = threadIdx.x & 31;
    const int e = warp;

    int cnt = 0;
    for (int base = 0; base < NTOK; base += 32) {
        const int t = base + lane;
        bool match = false;
        #pragma unroll
        for (int kk = 0; kk < TOPK; kk++) match |= (g_topk_eid[t*TOPK + kk] == e);
        cnt += __popc(__ballot_sync(0xffffffffu, match));
    }
    if (lane == 0) counts[e] = cnt;
    __syncthreads();
    if (threadIdx.x == 0) {
        int acc = 0;
        for (int i = 0; i < NE; i++) { offs[i] = acc; acc += counts[i]; }
        offs[NE] = acc;
        for (int i = 0; i <= NE; i++) g_expert_off[i] = offs[i];
    }
    __syncthreads();

    int run = offs[e];
    for (int base = 0; base < NTOK; base += 32) {
        const int t = base + lane;
        int kkm = -1;
        #pragma unroll
        for (int kk = 0; kk < TOPK; kk++)
            if (g_topk_eid[t*TOPK + kk] == e) kkm = kk;
        unsigned mask = __ballot_sync(0xffffffffu, kkm >= 0);
        int rank = __popc(mask & ((1u << lane) - 1u));
        if (kkm >= 0) {
            int slot = run + rank;
            g_slot_token[slot] = t;
            g_token_slot[t*TOPK + kkm] = slot;
        }
        run += __popc(mask);
    }
}

// ---------------- shared GEMM geometry --------------------------------------
// BM=128, BN=128, BK=32, 256 thr = 8 warps (2m x 4n), warp tile 64x32.
#define BK      32
#define KSTRIDE 36          // padded row stride in floats
#define ASZ     (128*KSTRIDE)
#define SMEM_TC (4*ASZ*4)   // A(2 bufs) + B(2 bufs), bytes = 73728

// ---------------- 3. GEMM1: gu = X @ w1^T, fused activation -----------------
__global__ __launch_bounds__(256) void gemm1_tc(
    const float* __restrict__ hidden,
    const float* __restrict__ w1,
    const float* __restrict__ b1)
{
    const int e   = blockIdx.z;
    const int off = g_expert_off[e];
    const int cnt = g_expert_off[e+1] - off;
    const int m0  = blockIdx.y * 128;
    if (m0 >= cnt) return;
    const int n0  = blockIdx.x * 128;
    const int tid = threadIdx.x, wid = tid >> 5, lane = tid & 31;
    const int wm = wid & 1, wn = wid >> 1;
    const int lr = lane >> 2, lc = lane & 3;

    extern __shared__ float sm[];
    float* Asm = sm;            // 2 buffers
    float* Bsm = sm + 2*ASZ;    // 2 buffers

    // loader geometry: thread -> (row = tid>>1, 16-float half = tid&1)
    const int lrow = tid >> 1;
    const int lk16 = (tid & 1) * 16;
    int amrow = m0 + lrow; if (amrow >= cnt) amrow = cnt - 1;
    const int atok = g_slot_token[off + amrow];
    const float* __restrict__ aptr = hidden + (size_t)atok * HD + lk16;
    const float* __restrict__ bptr = w1 + ((size_t)e * 2*ID + (size_t)(n0 + lrow)) * HD + lk16;
    float* asts = Asm + lrow*KSTRIDE + lk16;
    float* bsts = Bsm + lrow*KSTRIDE + lk16;

    float acc[4][4][4];
    #pragma unroll
    for (int i = 0; i < 4; i++)
        #pragma unroll
        for (int j = 0; j < 4; j++)
            #pragma unroll
            for (int q = 0; q < 4; q++) acc[i][j][q] = 0.f;

    const int C = HD / BK;   // 90

    // preload chunk 0
    float4 ar[4], br[4];
    #pragma unroll
    for (int j = 0; j < 4; j++) { ar[j] = *(const float4*)(aptr + j*4); br[j] = *(const float4*)(bptr + j*4); }
    #pragma unroll
    for (int j = 0; j < 4; j++) { cvt_store4(asts + j*4, ar[j]); cvt_store4(bsts + j*4, br[j]); }
    __syncthreads();

    for (int c = 0; c < C; c++) {
        const int buf = c & 1;
        if (c + 1 < C) {
            const int k0 = (c + 1) * BK;
            #pragma unroll
            for (int j = 0; j < 4; j++) {
                ar[j] = *(const float4*)(aptr + k0 + j*4);
                br[j] = *(const float4*)(bptr + k0 + j*4);
            }
        }
        const float* A = Asm + buf*ASZ;
        const float* B = Bsm + buf*ASZ;
        #pragma unroll
        for (int ks = 0; ks < 4; ks++) {
            uint32_t af[4][4], bf[4][2];
            #pragma unroll
            for (int mt = 0; mt < 4; mt++) {
                const float* p = A + (wm*64 + mt*16 + lr)*KSTRIDE + ks*8 + lc;
                af[mt][0] = __float_as_uint(p[0]);
                af[mt][1] = __float_as_uint(p[8*KSTRIDE]);
                af[mt][2] = __float_as_uint(p[4]);
                af[mt][3] = __float_as_uint(p[8*KSTRIDE + 4]);
            }
            #pragma unroll
            for (int nt = 0; nt < 4; nt++) {
                const float* p = B + (wn*32 + nt*8 + lr)*KSTRIDE + ks*8 + lc;
                bf[nt][0] = __float_as_uint(p[0]);
                bf[nt][1] = __float_as_uint(p[4]);
            }
            #pragma unroll
            for (int mt = 0; mt < 4; mt++)
                #pragma unroll
                for (int nt = 0; nt < 4; nt++)
                    mma_tf32_16n8k8(acc[mt][nt], af[mt], bf[nt]);
        }
        __syncthreads();
        if (c + 1 < C) {
            const int nb = (c + 1) & 1;
            #pragma unroll
            for (int j = 0; j < 4; j++) {
                cvt_store4(asts + nb*ASZ + j*4, ar[j]);
                cvt_store4(bsts + nb*ASZ + j*4, br[j]);
            }
            __syncthreads();
        }
    }

    // epilogue: c0/c1 are adjacent even/odd columns = (gate, up) pair
    const float* __restrict__ b1e = b1 + (size_t)e * 2*ID;
    #pragma unroll
    for (int mt = 0; mt < 4; mt++) {
        const int mrow0 = m0 + wm*64 + mt*16 + lr;
        #pragma unroll
        for (int half = 0; half < 2; half++) {
            const int m = mrow0 + half*8;
            if (m >= cnt) continue;
            float* __restrict__ arow = g_act + (size_t)(off + m) * ID;
            #pragma unroll
            for (int nt = 0; nt < 4; nt++) {
                const int ng = n0 + wn*32 + nt*8 + lc*2;
                float g = acc[mt][nt][2*half]     + b1e[ng];
                float u = acc[mt][nt][2*half + 1] + b1e[ng + 1];
                g = fminf(g, LIMITC);
                u = fminf(fmaxf(u, -LIMITC), LIMITC);
                float sig = 1.f / (1.f + __expf(-ALPHAC * g));
                arow[ng >> 1] = (u + 1.f) * (g * sig);
            }
        }
    }
}

// ---------------- 4. GEMM2: out_e = act @ w2^T + b2 -------------------------
__global__ __launch_bounds__(256) void gemm2_tc(
    const float* __restrict__ w2,
    const float* __restrict__ b2)
{
    const int e   = blockIdx.z;
    const int off = g_expert_off[e];
    const int cnt = g_expert_off[e+1] - off;
    const int m0  = blockIdx.y * 128;
    if (m0 >= cnt) return;
    const int n0  = blockIdx.x * 128;
    const int tid = threadIdx.x, wid = tid >> 5, lane = tid & 31;
    const int wm = wid & 1, wn = wid >> 1;
    const int lr = lane >> 2, lc = lane & 3;

    extern __shared__ float sm[];
    float* Asm = sm;
    float* Bsm = sm + 2*ASZ;

    const int lrow = tid >> 1;
    const int lk16 = (tid & 1) * 16;
    int amrow = m0 + lrow; if (amrow >= cnt) amrow = cnt - 1;
    int bnrow = n0 + lrow; if (bnrow >= HD)  bnrow = HD - 1;
    const float* __restrict__ aptr = g_act + (size_t)(off + amrow) * ID + lk16;
    const float* __restrict__ bptr = w2 + ((size_t)e * HD + (size_t)bnrow) * ID + lk16;
    float* asts = Asm + lrow*KSTRIDE + lk16;
    float* bsts = Bsm + lrow*KSTRIDE + lk16;

    float acc[4][4][4];
    #pragma unroll
    for (int i = 0; i < 4; i++)
        #pragma unroll
        for (int j = 0; j < 4; j++)
            #pragma unroll
            for (int q = 0; q < 4; q++) acc[i][j][q] = 0.f;

    const int C = ID / BK;   // 90

    float4 ar[4], br[4];
    #pragma unroll
    for (int j = 0; j < 4; j++) { ar[j] = *(const float4*)(aptr + j*4); br[j] = *(const float4*)(bptr + j*4); }
    #pragma unroll
    for (int j = 0; j < 4; j++) { cvt_store4(asts + j*4, ar[j]); cvt_store4(bsts + j*4, br[j]); }
    __syncthreads();

    for (int c = 0; c < C; c++) {
        const int buf = c & 1;
        if (c + 1 < C) {
            const int k0 = (c + 1) * BK;
            #pragma unroll
            for (int j = 0; j < 4; j++) {
                ar[j] = *(const float4*)(aptr + k0 + j*4);
                br[j] = *(const float4*)(bptr + k0 + j*4);
            }
        }
        const float* A = Asm + buf*ASZ;
        const float* B = Bsm + buf*ASZ;
        #pragma unroll
        for (int ks = 0; ks < 4; ks++) {
            uint32_t af[4][4], bf[4][2];
            #pragma unroll
            for (int mt = 0; mt < 4; mt++) {
                const float* p = A + (wm*64 + mt*16 + lr)*KSTRIDE + ks*8 + lc;
                af[mt][0] = __float_as_uint(p[0]);
                af[mt][1] = __float_as_uint(p[8*KSTRIDE]);
                af[mt][2] = __float_as_uint(p[4]);
                af[mt][3] = __float_as_uint(p[8*KSTRIDE + 4]);
            }
            #pragma unroll
            for (int nt = 0; nt < 4; nt++) {
                const float* p = B + (wn*32 + nt*8 + lr)*KSTRIDE + ks*8 + lc;
                bf[nt][0] = __float_as_uint(p[0]);
                bf[nt][1] = __float_as_uint(p[4]);
            }
            #pragma unroll
            for (int mt = 0; mt < 4; mt++)
                #pragma unroll
                for (int nt = 0; nt < 4; nt++)
                    mma_tf32_16n8k8(acc[mt][nt], af[mt], bf[nt]);
        }
        __syncthreads();
        if (c + 1 < C) {
            const int nb = (c + 1) & 1;
            #pragma unroll
            for (int j = 0; j < 4; j++) {
                cvt_store4(asts + nb*ASZ + j*4, ar[j]);
                cvt_store4(bsts + nb*ASZ + j*4, br[j]);
            }
            __syncthreads();
        }
    }

    const float* __restrict__ b2e = b2 + (size_t)e * HD;
    #pragma unroll
    for (int mt = 0; mt < 4; mt++) {
        const int mrow0 = m0 + wm*64 + mt*16 + lr;
        #pragma unroll
        for (int half = 0; half < 2; half++) {
            const int m = mrow0 + half*8;
            if (m >= cnt) continue;
            float* __restrict__ orow = g_out2 + (size_t)(off + m) * HD;
            #pragma unroll
            for (int nt = 0; nt < 4; nt++) {
                const int n = n0 + wn*32 + nt*8 + lc*2;
                if (n < HD) {
                    orow[n]     = acc[mt][nt][2*half]     + b2e[n];
                    orow[n + 1] = acc[mt][nt][2*half + 1] + b2e[n + 1];
                }
            }
        }
    }
}

// ---------------- 5. combine ------------------------------------------------
__global__ __launch_bounds__(256) void combine_kernel(float* __restrict__ out)
{
    const int t = blockIdx.x;
    __shared__ int   ss[TOPK];
    __shared__ float pp[TOPK];
    if (threadIdx.x < TOPK) {
        ss[threadIdx.x] = g_token_slot[t*TOPK + threadIdx.x];
        pp[threadIdx.x] = g_topk_prob[t*TOPK + threadIdx.x];
    }
    __syncthreads();
    const int   s0 = ss[0], s1 = ss[1], s2 = ss[2], s3 = ss[3];
    const float p0 = pp[0], p1 = pp[1], p2 = pp[2], p3 = pp[3];
    const float* __restrict__ r0 = g_out2 + (size_t)s0 * HD;
    const float* __restrict__ r1 = g_out2 + (size_t)s1 * HD;
    const float* __restrict__ r2 = g_out2 + (size_t)s2 * HD;
    const float* __restrict__ r3 = g_out2 + (size_t)s3 * HD;
    float* __restrict__ o = out + (size_t)t * HD;
    for (int h = threadIdx.x; h < HD; h += blockDim.x) {
        o[h] = p0*r0[h] + p1*r1[h] + p2*r2[h] + p3*r3[h];
    }
}

// ---------------- launch ----------------------------------------------------
extern "C" void kernel_launch(void* const* d_in, const int* in_sizes, int n_in,
                              void* d_out, int out_size)
{
    const float* hidden   = (const float*)d_in[0];
    const float* router_w = (const float*)d_in[1];
    const float* router_b = (const float*)d_in[2];
    const float* w1       = (const float*)d_in[3];
    const float* b1       = (const float*)d_in[4];
    const float* w2       = (const float*)d_in[5];
    const float* b2       = (const float*)d_in[6];
    float* out = (float*)d_out;

    cudaFuncSetAttribute(gemm1_tc, cudaFuncAttributeMaxDynamicSharedMemorySize, SMEM_TC);
    cudaFuncSetAttribute(gemm2_tc, cudaFuncAttributeMaxDynamicSharedMemorySize, SMEM_TC);

    router_kernel<<<NTOK, 256>>>(hidden, router_w, router_b);
    build_kernel<<<1, 512>>>();
    gemm1_tc<<<dim3(45, 8, NE), 256, SMEM_TC>>>(hidden, w1, b1);  // 5760/128
    gemm2_tc<<<dim3(23, 8, NE), 256, SMEM_TC>>>(w2, b2);          // ceil(2880/128)
    combine_kernel<<<NTOK, 256>>>(out);
}